// round 4
// baseline (speedup 1.0000x reference)
#include <cuda_runtime.h>

#define B_      32
#define DIM_    4096
#define NH_     32
#define NKV_    8
#define HD_     128
#define NREP_   4
#define T_TOT   2048
#define START_  2047
#define QKV_N   6144
#define SK_     8
#define TILE_N  128
#define TILE_K  32
#define SPLITS_ 4
#define TOK_PER_SPLIT 512
#define TOK_PER_WARP  128
#define NPART_  16   // SPLITS_ * 4 warps

// ---------------- scratch (device globals; no runtime allocation) ----------
__device__ float g_part[SK_ * B_ * QKV_N];          // GEMM split-K partials (6 MB)
__device__ float g_qkv [B_ * QKV_N];                // fused q|k|v after reduce (cols: 0..4095 q, 4096..5119 k, 5120..6143 v)
__device__ float g_attn[B_ * NH_ * HD_];            // attention output (b, h*128+d)
__device__ float g_pm  [B_ * NH_ * NPART_];
__device__ float g_pl  [B_ * NH_ * NPART_];
__device__ float g_po  [(size_t)B_ * NH_ * NPART_ * HD_];  // 32 MB

// ---------------- split-K tall-skinny GEMM: [32,K] @ [K,N] -> g_part -------
__device__ __forceinline__ void gemm_body(const float* __restrict__ A,
                                          const float* __restrict__ W,
                                          int N, int col0)
{
    __shared__ float xs[TILE_K][B_ + 1];    // xs[kk][b]
    __shared__ float ws[TILE_K][TILE_N];

    const int n0  = blockIdx.x * TILE_N;
    const int ky  = blockIdx.y;
    const int kbeg = ky * (DIM_ / SK_);      // 512 per split
    const int tid = threadIdx.x;
    const int tx  = tid & 31;
    const int ty  = tid >> 5;

    float acc[4][4];
#pragma unroll
    for (int i = 0; i < 4; i++)
#pragma unroll
        for (int j = 0; j < 4; j++) acc[i][j] = 0.f;

    for (int kt = 0; kt < DIM_ / SK_; kt += TILE_K) {
        const int k0 = kbeg + kt;
        // stage W chunk [32][128], coalesced along n
#pragma unroll
        for (int i = 0; i < (TILE_K * TILE_N) / 256; i++) {
            int idx = tid + i * 256;
            int kk = idx >> 7;
            int nn = idx & 127;
            ws[kk][nn] = W[(size_t)(k0 + kk) * N + n0 + nn];
        }
        // stage A chunk [32 batches][32 k]
#pragma unroll
        for (int i = 0; i < (B_ * TILE_K) / 256; i++) {
            int idx = tid + i * 256;
            int bb = idx >> 5;
            int kk = idx & 31;
            xs[kk][bb] = A[(size_t)bb * DIM_ + k0 + kk];
        }
        __syncthreads();
#pragma unroll
        for (int kk = 0; kk < TILE_K; kk++) {
            float xv[4], wv[4];
#pragma unroll
            for (int i = 0; i < 4; i++) xv[i] = xs[kk][ty + 8 * i];
#pragma unroll
            for (int j = 0; j < 4; j++) wv[j] = ws[kk][tx + 32 * j];
#pragma unroll
            for (int i = 0; i < 4; i++)
#pragma unroll
                for (int j = 0; j < 4; j++) acc[i][j] += xv[i] * wv[j];
        }
        __syncthreads();
    }
#pragma unroll
    for (int i = 0; i < 4; i++) {
        int bb = ty + 8 * i;
#pragma unroll
        for (int j = 0; j < 4; j++) {
            int nn = col0 + n0 + tx + 32 * j;
            g_part[((size_t)ky * B_ + bb) * QKV_N + nn] = acc[i][j];
        }
    }
}

__global__ void gemm_x(const float* __restrict__ A, const float* __restrict__ W,
                       int N, int col0)
{
    gemm_body(A, W, N, col0);
}

__global__ void gemm_attn(const float* __restrict__ W)
{
    gemm_body(g_attn, W, 4096, 0);
}

// ---------------- reduces -------------------------------------------------
__global__ void reduce_qkv()
{
    int i = blockIdx.x * blockDim.x + threadIdx.x;   // over 32*6144
    float s = 0.f;
#pragma unroll
    for (int ky = 0; ky < SK_; ky++)
        s += g_part[(size_t)ky * (B_ * QKV_N) + i];
    g_qkv[i] = s;
}

__global__ void reduce_wo(float* __restrict__ out)
{
    int i = blockIdx.x * blockDim.x + threadIdx.x;   // over 32*4096
    int bb = i >> 12;
    int nn = i & 4095;
    float s = 0.f;
#pragma unroll
    for (int ky = 0; ky < SK_; ky++)
        s += g_part[((size_t)ky * B_ + bb) * QKV_N + nn];
    out[i] = s;
}

// ---------------- RoPE on q (32 heads) and k (8 heads), in place ----------
__global__ void rope_kernel(const float* __restrict__ fc, const float* __restrict__ fs)
{
    int idx = blockIdx.x * blockDim.x + threadIdx.x;   // 81920 pairs total
    if (idx >= 81920) return;
    int off, i;
    if (idx < 65536) {                                  // q: b*32 heads*64 pairs
        int bb  = idx >> 11;
        int rem = idx & 2047;
        int h   = rem >> 6;
        i       = rem & 63;
        off = bb * QKV_N + h * HD_ + 2 * i;
    } else {                                            // k: b*8 heads*64 pairs
        int j   = idx - 65536;
        int bb  = j >> 9;
        int rem = j & 511;
        int h   = rem >> 6;
        i       = rem & 63;
        off = bb * QKV_N + 4096 + h * HD_ + 2 * i;
    }
    float c = fc[i], s = fs[i];
    float xr = g_qkv[off], xi = g_qkv[off + 1];
    g_qkv[off]     = xr * c - xi * s;
    g_qkv[off + 1] = xr * s + xi * c;
}

// ---------------- flash-decode attention ----------------------------------
// grid: b(32) * g(8) * split(4) blocks, 128 threads.
// Each warp owns 128 contiguous tokens; online softmax per (warp, head);
// new token (t==2047) read from g_qkv instead of the caches.
__global__ void attn_kernel(const float* __restrict__ kc, const float* __restrict__ vc)
{
    const int blk = blockIdx.x;
    const int sp  = blk & 3;
    const int g   = (blk >> 2) & 7;
    const int bb  = blk >> 5;
    const int tid = threadIdx.x;
    const int w   = tid >> 5;
    const int lane = tid & 31;

    __shared__ float q_s[NREP_][HD_];
    for (int idx = tid; idx < NREP_ * HD_; idx += 128) {
        int h = idx >> 7, d = idx & 127;
        q_s[h][d] = g_qkv[bb * QKV_N + (g * NREP_ + h) * HD_ + d];
    }
    __syncthreads();

    const float scale = 0.08838834764831845f;   // 1/sqrt(128)
    float m[4], l[4], acc[4][4];
#pragma unroll
    for (int h = 0; h < 4; h++) {
        m[h] = -1e30f; l[h] = 0.f;
#pragma unroll
        for (int j = 0; j < 4; j++) acc[h][j] = 0.f;
    }

    const int tbase = sp * TOK_PER_SPLIT + w * TOK_PER_WARP;
    const float* knew = &g_qkv[bb * QKV_N + 4096 + g * HD_];
    const float* vnew = &g_qkv[bb * QKV_N + 5120 + g * HD_];

    for (int r = 0; r < 4; r++) {
        const int t = tbase + r * 32 + lane;
        const float* krow;
        if (t == START_) {
            krow = knew;
        } else {
            krow = kc + (((size_t)bb * T_TOT + t) * NKV_ + g) * HD_;
        }
        // scores: each lane does a full dot for its token, for all 4 heads
        float s4[4] = {0.f, 0.f, 0.f, 0.f};
#pragma unroll
        for (int i = 0; i < HD_ / 4; i++) {
            float4 k4 = __ldg(reinterpret_cast<const float4*>(krow) + i);
#pragma unroll
            for (int h = 0; h < 4; h++) {
                float4 q4 = *(reinterpret_cast<const float4*>(&q_s[h][0]) + i);
                s4[h] += k4.x * q4.x + k4.y * q4.y + k4.z * q4.z + k4.w * q4.w;
            }
        }
        float p[4];
#pragma unroll
        for (int h = 0; h < 4; h++) {
            float sc = s4[h] * scale;
            float mx = sc;
#pragma unroll
            for (int o = 16; o > 0; o >>= 1)
                mx = fmaxf(mx, __shfl_xor_sync(0xffffffffu, mx, o));
            float mnew = fmaxf(m[h], mx);
            float corr = __expf(m[h] - mnew);
            p[h] = __expf(sc - mnew);
            float ps = p[h];
#pragma unroll
            for (int o = 16; o > 0; o >>= 1)
                ps += __shfl_xor_sync(0xffffffffu, ps, o);
            l[h] = l[h] * corr + ps;
            m[h] = mnew;
#pragma unroll
            for (int j = 0; j < 4; j++) acc[h][j] *= corr;
        }
        // V accumulation: lane owns dims d = lane*4..lane*4+3 (coalesced rows)
#pragma unroll 4
        for (int tt = 0; tt < 32; tt++) {
            const int t2 = tbase + r * 32 + tt;
            const float* vrow;
            if (t2 == START_) {
                vrow = vnew;
            } else {
                vrow = vc + (((size_t)bb * T_TOT + t2) * NKV_ + g) * HD_;
            }
            float4 v4 = __ldg(reinterpret_cast<const float4*>(vrow) + lane);
            float pt[4];
#pragma unroll
            for (int h = 0; h < 4; h++)
                pt[h] = __shfl_sync(0xffffffffu, p[h], tt);
#pragma unroll
            for (int h = 0; h < 4; h++) {
                acc[h][0] += pt[h] * v4.x;
                acc[h][1] += pt[h] * v4.y;
                acc[h][2] += pt[h] * v4.z;
                acc[h][3] += pt[h] * v4.w;
            }
        }
    }

    // write partials (one per warp per split -> 16 per (b, head))
    const int sp16 = sp * 4 + w;
#pragma unroll
    for (int h = 0; h < 4; h++) {
        const int hh = g * NREP_ + h;
        if (lane == 0) {
            g_pm[(bb * NH_ + hh) * NPART_ + sp16] = m[h];
            g_pl[(bb * NH_ + hh) * NPART_ + sp16] = l[h];
        }
        float4 o4 = make_float4(acc[h][0], acc[h][1], acc[h][2], acc[h][3]);
        reinterpret_cast<float4*>(
            &g_po[(((size_t)bb * NH_ + hh) * NPART_ + sp16) * HD_])[lane] = o4;
    }
}

// ---------------- combine 16 partials per (b, head) ------------------------
__global__ void combine_kernel()
{
    const int bh = blockIdx.x;       // b*NH + h
    const int d  = threadIdx.x;      // 128
    float mx = -1e30f;
#pragma unroll
    for (int s = 0; s < NPART_; s++)
        mx = fmaxf(mx, g_pm[bh * NPART_ + s]);
    float lsum = 0.f, osum = 0.f;
#pragma unroll
    for (int s = 0; s < NPART_; s++) {
        float wgt = __expf(g_pm[bh * NPART_ + s] - mx);
        lsum += g_pl[bh * NPART_ + s] * wgt;
        osum += wgt * g_po[((size_t)bh * NPART_ + s) * HD_ + d];
    }
    g_attn[bh * HD_ + d] = osum / lsum;
}

// ---------------- launch ----------------------------------------------------
extern "C" void kernel_launch(void* const* d_in, const int* in_sizes, int n_in,
                              void* d_out, int out_size)
{
    (void)in_sizes; (void)n_in; (void)out_size;
    const float* x  = (const float*)d_in[0];
    const float* wq = (const float*)d_in[1];
    const float* wk = (const float*)d_in[2];
    const float* wv = (const float*)d_in[3];
    const float* wo = (const float*)d_in[4];
    const float* kc = (const float*)d_in[5];
    const float* vc = (const float*)d_in[6];
    const float* fc = (const float*)d_in[7];
    const float* fs = (const float*)d_in[8];
    float* out = (float*)d_out;

    // QKV projection (split-K partials)
    gemm_x<<<dim3(4096 / TILE_N, SK_), 256>>>(x, wq, 4096, 0);
    gemm_x<<<dim3(1024 / TILE_N, SK_), 256>>>(x, wk, 1024, 4096);
    gemm_x<<<dim3(1024 / TILE_N, SK_), 256>>>(x, wv, 1024, 5120);
    reduce_qkv<<<(B_ * QKV_N) / 256, 256>>>();

    // RoPE on q and k
    rope_kernel<<<81920 / 256, 256>>>(fc, fs);

    // flash-decode attention + combine
    attn_kernel<<<B_ * NKV_ * SPLITS_, 128>>>(kc, vc);
    combine_kernel<<<B_ * NH_, 128>>>();

    // output projection
    gemm_attn<<<dim3(4096 / TILE_N, SK_), 256>>>(wo);
    reduce_wo<<<(B_ * 4096) / 256, 256>>>(out);
}

// round 6
// speedup vs baseline: 1.6018x; 1.6018x over previous
#include <cuda_runtime.h>

#define B_      32
#define DIM_    4096
#define NH_     32
#define NKV_    8
#define HD_     128
#define NREP_   4
#define T_TOT   2048
#define START_  2047
#define QKV_N   6144
#define SK_     8
#define TILE_N  128
#define TILE_K  32
#define SPLITS_ 4
#define TOK_PER_SPLIT 512
#define TOK_PER_WARP  128
#define NPART_  16   // SPLITS_ * 4 warps

typedef unsigned long long ull;

// ---------------- scratch (device globals; no runtime allocation) ----------
__device__ float g_part[SK_ * B_ * QKV_N];          // GEMM split-K partials
__device__ float g_qkv [B_ * QKV_N];                // fused q|k|v after reduce+rope
__device__ float g_attn[B_ * NH_ * HD_];            // attention output
__device__ float g_pm  [B_ * NH_ * NPART_];
__device__ float g_pl  [B_ * NH_ * NPART_];
__device__ float g_po  [(size_t)B_ * NH_ * NPART_ * HD_];

// packed fp32x2 FMA: d += a * b (elementwise on pairs). ptxas never emits
// FFMA2 from C++; PTX fma.rn.f32x2 is the only route (2x fp32 throughput).
__device__ __forceinline__ void ffma2(ull& d, ull a, ull b)
{
    asm("fma.rn.f32x2 %0, %1, %2, %0;" : "+l"(d) : "l"(a), "l"(b));
}

// ---------------- split-K tall-skinny GEMM with K-pair FFMA2 ---------------
// block: 128 threads, computes [32 x 128] over K-slice of 512.
// Thread tile: 4 rows x 8 cols, accumulated as f32x2 pairs along K.
__device__ __forceinline__ void gemm_body(const float* __restrict__ A,
                                          const float* __restrict__ W,
                                          int N, int col0, int n0, int ky)
{
    __shared__ float xs[B_][TILE_K + 2];      // [b][k]   (row len 34: even, 8B-aligned)
    __shared__ float ws[TILE_N][TILE_K + 2];  // [n][k]   transposed weight tile

    const int kbeg = ky * (DIM_ / SK_);       // 512 per split
    const int tid  = threadIdx.x;
    const int tx   = tid & 15;                // 0..15 -> col groups
    const int ty   = tid >> 4;                // 0..7  -> row groups

    ull acc[4][8];
#pragma unroll
    for (int i = 0; i < 4; i++)
#pragma unroll
        for (int j = 0; j < 8; j++) acc[i][j] = 0ull;

    for (int kt = 0; kt < DIM_ / SK_; kt += TILE_K) {
        const int k0 = kbeg + kt;
        // stage W tile transposed: ws[nn][kk] <- W[k0+kk][n0+nn]
#pragma unroll
        for (int it = 0; it < (TILE_K * TILE_N) / 128; it++) {
            int idx = tid + it * 128;
            int kk = idx >> 7;
            int nn = idx & 127;
            ws[nn][kk] = W[(size_t)(k0 + kk) * N + n0 + nn];
        }
        // stage A tile: xs[bb][kk] <- A[bb][k0+kk]
#pragma unroll
        for (int it = 0; it < (B_ * TILE_K) / 128; it++) {
            int idx = tid + it * 128;
            int bb = idx >> 5;
            int kk = idx & 31;
            xs[bb][kk] = A[(size_t)bb * DIM_ + k0 + kk];
        }
        __syncthreads();
#pragma unroll
        for (int kp = 0; kp < TILE_K / 2; kp++) {
            ull xv[4], wv[8];
#pragma unroll
            for (int i = 0; i < 4; i++)
                xv[i] = *reinterpret_cast<const ull*>(&xs[ty + 8 * i][2 * kp]);
#pragma unroll
            for (int j = 0; j < 8; j++)
                wv[j] = *reinterpret_cast<const ull*>(&ws[tx + 16 * j][2 * kp]);
#pragma unroll
            for (int i = 0; i < 4; i++)
#pragma unroll
                for (int j = 0; j < 8; j++)
                    ffma2(acc[i][j], xv[i], wv[j]);
        }
        __syncthreads();
    }
    // horizontal add of pair accumulators, write partials
#pragma unroll
    for (int i = 0; i < 4; i++) {
        int bb = ty + 8 * i;
#pragma unroll
        for (int j = 0; j < 8; j++) {
            float2 v = *reinterpret_cast<const float2*>(&acc[i][j]);
            int nn = col0 + n0 + tx + 16 * j;
            g_part[((size_t)ky * B_ + bb) * QKV_N + nn] = v.x + v.y;
        }
    }
}

// merged QKV projection: blockIdx.x = tile (0..47), blockIdx.y = ky
__global__ void __launch_bounds__(128)
gemm_qkv(const float* __restrict__ x, const float* __restrict__ wq,
         const float* __restrict__ wk, const float* __restrict__ wv)
{
    const int tile = blockIdx.x;
    const int ky   = blockIdx.y;
    if (tile < 32)       gemm_body(x, wq, 4096, 0,    tile * TILE_N,        ky);
    else if (tile < 40)  gemm_body(x, wk, 1024, 4096, (tile - 32) * TILE_N, ky);
    else                 gemm_body(x, wv, 1024, 5120, (tile - 40) * TILE_N, ky);
}

__global__ void __launch_bounds__(128)
gemm_o(const float* __restrict__ W)
{
    gemm_body(g_attn, W, 4096, 0, blockIdx.x * TILE_N, blockIdx.y);
}

// ---------------- fused reduce + RoPE (float2 pairs) -----------------------
__global__ void reduce_rope(const float* __restrict__ fc, const float* __restrict__ fs)
{
    const int i = blockIdx.x * blockDim.x + threadIdx.x;  // pair index over 32*3072
    const int bb = i >> 11;      // i / 3072? no: 3072 not pow2
    // recompute correctly:
    const int idx = i;
    const int b2  = idx / 3072;
    const int cp  = idx - b2 * 3072;        // pair within row (0..3071)
    float2 s = make_float2(0.f, 0.f);
#pragma unroll
    for (int ky = 0; ky < SK_; ky++) {
        float2 v = reinterpret_cast<const float2*>(g_part)[(size_t)(ky * B_ + b2) * 3072 + cp];
        s.x += v.x; s.y += v.y;
    }
    if (cp < 2560) {  // q (cp<2048) and k (2048..2559) get RoPE
        int f = cp & 63;
        float c = fc[f], sn = fs[f];
        float xr = s.x, xi = s.y;
        s.x = xr * c - xi * sn;
        s.y = xr * sn + xi * c;
    }
    reinterpret_cast<float2*>(g_qkv)[(size_t)b2 * 3072 + cp] = s;
    (void)bb;
}

__global__ void reduce_wo(float* __restrict__ out)
{
    const int i = blockIdx.x * blockDim.x + threadIdx.x;  // float4 over 32*1024
    const int b2 = i >> 10;
    const int nn = i & 1023;
    float4 s = make_float4(0.f, 0.f, 0.f, 0.f);
#pragma unroll
    for (int ky = 0; ky < SK_; ky++) {
        float4 v = reinterpret_cast<const float4*>(g_part)[(size_t)(ky * B_ + b2) * (QKV_N / 4) + nn];
        s.x += v.x; s.y += v.y; s.z += v.z; s.w += v.w;
    }
    reinterpret_cast<float4*>(out)[(size_t)b2 * 1024 + nn] = s;
}

// ---------------- flash-decode attention ----------------------------------
__global__ void __launch_bounds__(128)
attn_kernel(const float* __restrict__ kc, const float* __restrict__ vc)
{
    const int blk = blockIdx.x;
    const int sp  = blk & 3;
    const int g   = (blk >> 2) & 7;
    const int bb  = blk >> 5;
    const int tid = threadIdx.x;
    const int w   = tid >> 5;
    const int lane = tid & 31;

    __shared__ float q_s[NREP_][HD_];
    for (int idx = tid; idx < NREP_ * HD_; idx += 128) {
        int h = idx >> 7, d = idx & 127;
        q_s[h][d] = g_qkv[bb * QKV_N + (g * NREP_ + h) * HD_ + d];
    }
    __syncthreads();

    const float scale = 0.08838834764831845f;   // 1/sqrt(128)
    float m[4], l[4], acc[4][4];
#pragma unroll
    for (int h = 0; h < 4; h++) {
        m[h] = -1e30f; l[h] = 0.f;
#pragma unroll
        for (int j = 0; j < 4; j++) acc[h][j] = 0.f;
    }

    const int tbase = sp * TOK_PER_SPLIT + w * TOK_PER_WARP;
    const float* knew = &g_qkv[bb * QKV_N + 4096 + g * HD_];
    const float* vnew = &g_qkv[bb * QKV_N + 5120 + g * HD_];

    for (int r = 0; r < 4; r++) {
        const int tb = tbase + r * 32;
        const int t = tb + lane;
        const float* krow = (t == START_)
            ? knew
            : kc + (((size_t)bb * T_TOT + t) * NKV_ + g) * HD_;

        float s4[4] = {0.f, 0.f, 0.f, 0.f};
#pragma unroll
        for (int i = 0; i < HD_ / 4; i++) {
            float4 k4 = __ldg(reinterpret_cast<const float4*>(krow) + i);
#pragma unroll
            for (int h = 0; h < 4; h++) {
                float4 q4 = *(reinterpret_cast<const float4*>(&q_s[h][0]) + i);
                s4[h] += k4.x * q4.x + k4.y * q4.y + k4.z * q4.z + k4.w * q4.w;
            }
        }
        float p[4];
#pragma unroll
        for (int h = 0; h < 4; h++) {
            float sc = s4[h] * scale;
            float mx = sc;
#pragma unroll
            for (int o = 16; o > 0; o >>= 1)
                mx = fmaxf(mx, __shfl_xor_sync(0xffffffffu, mx, o));
            float mnew = fmaxf(m[h], mx);
            float corr = __expf(m[h] - mnew);
            p[h] = __expf(sc - mnew);
            float ps = p[h];
#pragma unroll
            for (int o = 16; o > 0; o >>= 1)
                ps += __shfl_xor_sync(0xffffffffu, ps, o);
            l[h] = l[h] * corr + ps;
            m[h] = mnew;
#pragma unroll
            for (int j = 0; j < 4; j++) acc[h][j] *= corr;
        }
        // V accumulation: batch-load 8 rows at a time for MLP, then consume
#pragma unroll
        for (int tt0 = 0; tt0 < 32; tt0 += 8) {
            float4 v8[8];
#pragma unroll
            for (int u = 0; u < 8; u++) {
                const int t2 = tb + tt0 + u;
                const float* vrow = (t2 == START_)
                    ? vnew
                    : vc + (((size_t)bb * T_TOT + t2) * NKV_ + g) * HD_;
                v8[u] = __ldg(reinterpret_cast<const float4*>(vrow) + lane);
            }
#pragma unroll
            for (int u = 0; u < 8; u++) {
                float pt[4];
#pragma unroll
                for (int h = 0; h < 4; h++)
                    pt[h] = __shfl_sync(0xffffffffu, p[h], tt0 + u);
#pragma unroll
                for (int h = 0; h < 4; h++) {
                    acc[h][0] += pt[h] * v8[u].x;
                    acc[h][1] += pt[h] * v8[u].y;
                    acc[h][2] += pt[h] * v8[u].z;
                    acc[h][3] += pt[h] * v8[u].w;
                }
            }
        }
    }

    const int sp16 = sp * 4 + w;
#pragma unroll
    for (int h = 0; h < 4; h++) {
        const int hh = g * NREP_ + h;
        if (lane == 0) {
            g_pm[(bb * NH_ + hh) * NPART_ + sp16] = m[h];
            g_pl[(bb * NH_ + hh) * NPART_ + sp16] = l[h];
        }
        float4 o4 = make_float4(acc[h][0], acc[h][1], acc[h][2], acc[h][3]);
        reinterpret_cast<float4*>(
            &g_po[(((size_t)bb * NH_ + hh) * NPART_ + sp16) * HD_])[lane] = o4;
    }
}

// ---------------- combine 16 partials per (b, head) ------------------------
__global__ void combine_kernel()
{
    const int bh = blockIdx.x;       // b*NH + h
    const int d  = threadIdx.x;      // 128
    float mx = -1e30f;
#pragma unroll
    for (int s = 0; s < NPART_; s++)
        mx = fmaxf(mx, g_pm[bh * NPART_ + s]);
    float lsum = 0.f, osum = 0.f;
#pragma unroll
    for (int s = 0; s < NPART_; s++) {
        float wgt = __expf(g_pm[bh * NPART_ + s] - mx);
        lsum += g_pl[bh * NPART_ + s] * wgt;
        osum += wgt * g_po[((size_t)bh * NPART_ + s) * HD_ + d];
    }
    g_attn[bh * HD_ + d] = osum / lsum;
}

// ---------------- launch ----------------------------------------------------
extern "C" void kernel_launch(void* const* d_in, const int* in_sizes, int n_in,
                              void* d_out, int out_size)
{
    (void)in_sizes; (void)n_in; (void)out_size;
    const float* x  = (const float*)d_in[0];
    const float* wq = (const float*)d_in[1];
    const float* wk = (const float*)d_in[2];
    const float* wv = (const float*)d_in[3];
    const float* wo = (const float*)d_in[4];
    const float* kc = (const float*)d_in[5];
    const float* vc = (const float*)d_in[6];
    const float* fc = (const float*)d_in[7];
    const float* fs = (const float*)d_in[8];
    float* out = (float*)d_out;

    // QKV projection, merged (48 col-tiles x 8 K-splits)
    gemm_qkv<<<dim3(48, SK_), 128>>>(x, wq, wk, wv);
    // reduce split-K partials + RoPE in one pass (32*3072 float2 pairs)
    reduce_rope<<<(B_ * 3072) / 256, 256>>>(fc, fs);

    // flash-decode attention + combine
    attn_kernel<<<B_ * NKV_ * SPLITS_, 128>>>(kc, vc);
    combine_kernel<<<B_ * NH_, 128>>>();

    // output projection
    gemm_o<<<dim3(32, SK_), 128>>>(wo);
    reduce_wo<<<(B_ * 1024) / 256, 256>>>(out);
}